// round 9
// baseline (speedup 1.0000x reference)
#include <cuda_runtime.h>

#define BB 8
#define NN 2048
#define BN (BB * NN)
#define CC 128
#define HH 4
#define DD 32
#define SS 3
#define KNB 16
#define KT 48
#define MT 64          // GEMM m-tile
#define APP 8          // points per attn block (1 warp each)
#define NJOB 54        // 48 nbr + 3 own + 3 bk
#define CAP 256        // knn candidate capacity per warp

#define FULLMASK 0xffffffffu
typedef unsigned long long ull;

__device__ int   g_knn[BN * KT];
__device__ float g_Q[BN * CC];
__device__ float g_V[BN * CC];
__device__ float g_KF[(SS * BN + SS) * CC];   // + SS rows of bk at the tail
__device__ ull   g_Wd[5 * CC * CC];           // duplicated-packed weights (w,w)

// ---- f32x2 packed-FMA helpers (full fp32 precision, 2 FMA / instr) --------
__device__ __forceinline__ ull pk2(float lo, float hi) {
    ull r; asm("mov.b64 %0, {%1,%2};" : "=l"(r) : "f"(lo), "f"(hi)); return r;
}
__device__ __forceinline__ void fma2(ull& d, ull a, ull b) {
    asm("fma.rn.f32x2 %0, %1, %2, %0;" : "+l"(d) : "l"(a), "l"(b));
}
__device__ __forceinline__ float2 upk2(ull v) {
    float2 f; asm("mov.b64 {%0,%1}, %2;" : "=f"(f.x), "=f"(f.y) : "l"(v)); return f;
}

// ---------------------------------------------------------------------------
// Kernel 0: prep — packed-duplicated weights + bk tail rows of g_KF.
// ---------------------------------------------------------------------------
__global__ __launch_bounds__(256) void prep_kernel(
    const float* __restrict__ Wq, const float* __restrict__ Wv,
    const float* __restrict__ Wk, const float* __restrict__ bk) {
    const int id = blockIdx.x * 256 + threadIdx.x;
    if (id < 5 * CC * CC) {
        int y = id >> 14, r = id & 16383;
        const float* Ws = (y == 0) ? Wq : (y == 1) ? Wv : Wk + (y - 2) * CC * CC;
        float w = Ws[r];
        g_Wd[id] = pk2(w, w);
    } else if (id - 5 * CC * CC < SS * CC) {
        int r = id - 5 * CC * CC;
        g_KF[(size_t)(SS * BN + r / CC) * CC + (r % CC)] = bk[r];
    }
}

// ---------------------------------------------------------------------------
// Shared-memory layouts for the fused kernel (union via dynamic smem)
// ---------------------------------------------------------------------------
struct KnnS {
    float4 c4[NN];          // (x, y, z, |p|^2)       32 KB
    ull    cand[8][CAP];    // compacted candidates   16 KB
    ull    buf[8][64];      // sort buffer             4 KB
};
struct GemmS { float XsT[CC][72]; };                // 36.9 KB

// ---------------------------------------------------------------------------
// kNN body: exact top-48 per query (one warp per query, 8 queries/block).
// ---------------------------------------------------------------------------
__device__ __forceinline__ void knn_body(char* smraw, const float* __restrict__ coord,
                                         int bx) {
    KnnS* K = (KnnS*)smraw;
    const int t = threadIdx.x;
    const int lane = t & 31, w = t >> 5;
    const int b = bx >> 8;                 // 256 blocks per batch
    const int n0 = (bx & 255) * 8;
    const float* cb = coord + (size_t)b * NN * 3;

    for (int j = t; j < NN; j += 256) {
        float x = cb[3 * j], y = cb[3 * j + 1], z = cb[3 * j + 2];
        K->c4[j] = make_float4(x, y, z, fmaf(x, x, fmaf(y, y, z * z)));
    }
    __syncthreads();

    const int n = n0 + w;
    const float4 o = K->c4[n];

    unsigned kkey[64];
    unsigned m1 = 0xffffffffu, m2 = 0xffffffffu;
    #pragma unroll
    for (int s = 0; s < 64; s++) {
        int j = lane + (s << 5);
        float4 c = K->c4[j];
        float dot = fmaf(o.x, c.x, fmaf(o.y, c.y, o.z * c.z));
        float d = fmaf(-2.0f, dot, o.w + c.w);         // matches reference formula
        unsigned u = __float_as_uint(d);
        u = u ^ (unsigned)(((int)u >> 31) | 0x80000000);  // monotone total order
        kkey[s] = u;
        if (u < m1) { m2 = m1; m1 = u; } else if (u < m2) { m2 = u; }
    }

    unsigned lo = __reduce_min_sync(FULLMASK, m1);
    unsigned hi = __reduce_max_sync(FULLMASK, m2);    // >= 64 keys <= hi

    // ---- compact all keys <= hi via prefix scan (lane-major order) ----
    int cnt = 0;
    #pragma unroll
    for (int s = 0; s < 64; s++) cnt += (kkey[s] <= hi) ? 1 : 0;
    int pre = cnt;
    #pragma unroll
    for (int off = 1; off < 32; off <<= 1) {
        int v = __shfl_up_sync(FULLMASK, pre, off);
        pre += (lane >= off) ? v : 0;
    }
    const int total = __shfl_sync(FULLMASK, pre, 31);
    if (total <= CAP) {
        int pos = pre - cnt;
        #pragma unroll
        for (int s = 0; s < 64; s++) {
            if (kkey[s] <= hi)
                K->cand[w][pos++] = ((ull)kkey[s] << 32) | (unsigned)(lane + (s << 5));
        }
    }
    __syncwarp();

    unsigned T;
    if (total <= CAP) {
        // ---- binary search over <= 8 candidates per lane ----
        unsigned ck[8];
        #pragma unroll
        for (int sl = 0; sl < 8; sl++) {
            int p = lane + (sl << 5);
            ck[sl] = (p < total) ? (unsigned)(K->cand[w][p] >> 32) : 0xffffffffu;
        }
        for (;;) {
            if (lo >= hi) { T = lo; break; }
            unsigned mid = lo + ((hi - lo) >> 1);
            unsigned c = 0;
            #pragma unroll
            for (int sl = 0; sl < 8; sl++) c += (ck[sl] <= mid) ? 1u : 0u;
            c = __reduce_add_sync(FULLMASK, c);
            if (c == KT) { T = mid; break; }
            if (c > KT) hi = mid; else lo = mid + 1;
        }
        // ---- collect <= T into buf via prefix scan ----
        K->buf[w][lane] = ~0ull;
        K->buf[w][lane + 32] = ~0ull;
        __syncwarp();
        int c2 = 0;
        #pragma unroll
        for (int sl = 0; sl < 8; sl++) c2 += (ck[sl] <= T) ? 1 : 0;
        int p2 = c2;
        #pragma unroll
        for (int off = 1; off < 32; off <<= 1) {
            int v = __shfl_up_sync(FULLMASK, p2, off);
            p2 += (lane >= off) ? v : 0;
        }
        int pos2 = p2 - c2;
        #pragma unroll
        for (int sl = 0; sl < 8; sl++) {
            if (ck[sl] <= T) {
                if (pos2 < 64) K->buf[w][pos2] = K->cand[w][lane + (sl << 5)];
                pos2++;
            }
        }
    } else {
        // ---- rare fallback: full 64-key search + ballot collect ----
        for (;;) {
            if (lo >= hi) { T = lo; break; }
            unsigned mid = lo + ((hi - lo) >> 1);
            unsigned c = 0;
            #pragma unroll
            for (int s = 0; s < 64; s++) c += (kkey[s] <= mid) ? 1u : 0u;
            c = __reduce_add_sync(FULLMASK, c);
            if (c == KT) { T = mid; break; }
            if (c > KT) hi = mid; else lo = mid + 1;
        }
        K->buf[w][lane] = ~0ull;
        K->buf[w][lane + 32] = ~0ull;
        __syncwarp();
        int bs = 0;
        #pragma unroll
        for (int s = 0; s < 64; s++) {
            bool q = (kkey[s] <= T);
            unsigned mm = __ballot_sync(FULLMASK, q);
            if (q) {
                int pos = bs + __popc(mm & ((1u << lane) - 1u));
                if (pos < 64)
                    K->buf[w][pos] = ((ull)kkey[s] << 32) | (unsigned)(lane + (s << 5));
            }
            bs += __popc(mm);
        }
    }
    __syncwarp();

    // ---- bitonic sort of 64 u64 keys, 2 per lane -> exact (dist, idx) order
    ull v0 = K->buf[w][lane];
    ull v1 = K->buf[w][lane + 32];
    #pragma unroll
    for (int k2 = 2; k2 <= 64; k2 <<= 1) {
        #pragma unroll
        for (int j2 = k2 >> 1; j2 > 0; j2 >>= 1) {
            if (j2 == 32) {
                ull a = v0 < v1 ? v0 : v1;
                ull bm = v0 < v1 ? v1 : v0;
                v0 = a; v1 = bm;
            } else {
                bool low = ((lane & j2) == 0);
                bool up0 = ((lane & k2) == 0);
                bool up1 = (((lane + 32) & k2) == 0);
                ull o0 = __shfl_xor_sync(FULLMASK, v0, j2);
                ull o1 = __shfl_xor_sync(FULLMASK, v1, j2);
                bool t0 = (low == up0);
                bool t1 = (low == up1);
                v0 = t0 ? (v0 < o0 ? v0 : o0) : (v0 > o0 ? v0 : o0);
                v1 = t1 ? (v1 < o1 ? v1 : o1) : (v1 > o1 ? v1 : o1);
            }
        }
    }

    int* outp = g_knn + ((size_t)b * NN + n) * KT;
    outp[lane] = (int)(v0 & 0xffffffffu);
    if (lane < KT - 32) outp[32 + lane] = (int)(v1 & 0xffffffffu);
}

// ---------------------------------------------------------------------------
// Register-tiled GEMM body: O[m0..m0+64][0..128) = A @ Wd + bias
// Wd is pre-duplicated packed f32x2 weights.
// ---------------------------------------------------------------------------
__device__ __forceinline__ void gemm_body(char* smraw,
                                          const float* __restrict__ A,
                                          const ull* __restrict__ Wd,
                                          const float* __restrict__ bias,
                                          float* __restrict__ O, int m0) {
    GemmS* G = (GemmS*)smraw;
    const int t = threadIdx.x;
    const int tx = t & 31, ty = t >> 5;

    #pragma unroll
    for (int s = t; s < MT * CC / 4; s += 256) {
        int m = s >> 5, k4 = s & 31;
        float4 v = *(const float4*)&A[(size_t)(m0 + m) * CC + 4 * k4];
        G->XsT[4 * k4 + 0][m] = v.x;
        G->XsT[4 * k4 + 1][m] = v.y;
        G->XsT[4 * k4 + 2][m] = v.z;
        G->XsT[4 * k4 + 3][m] = v.w;
    }
    __syncthreads();

    ull acc[4][4];
    #pragma unroll
    for (int mp = 0; mp < 4; mp++)
        #pragma unroll
        for (int c = 0; c < 4; c++) acc[mp][c] = 0;

    #pragma unroll 8
    for (int k = 0; k < CC; k++) {
        ulonglong2 wA = __ldg((const ulonglong2*)&Wd[k * CC + 4 * tx]);
        ulonglong2 wB = __ldg((const ulonglong2*)&Wd[k * CC + 4 * tx + 2]);
        ulonglong2 xa = *(const ulonglong2*)&G->XsT[k][ty * 8];
        ulonglong2 xb = *(const ulonglong2*)&G->XsT[k][ty * 8 + 4];
        fma2(acc[0][0], xa.x, wA.x); fma2(acc[0][1], xa.x, wA.y);
        fma2(acc[0][2], xa.x, wB.x); fma2(acc[0][3], xa.x, wB.y);
        fma2(acc[1][0], xa.y, wA.x); fma2(acc[1][1], xa.y, wA.y);
        fma2(acc[1][2], xa.y, wB.x); fma2(acc[1][3], xa.y, wB.y);
        fma2(acc[2][0], xb.x, wA.x); fma2(acc[2][1], xb.x, wA.y);
        fma2(acc[2][2], xb.x, wB.x); fma2(acc[2][3], xb.x, wB.y);
        fma2(acc[3][0], xb.y, wA.x); fma2(acc[3][1], xb.y, wA.y);
        fma2(acc[3][2], xb.y, wB.x); fma2(acc[3][3], xb.y, wB.y);
    }

    float4 bb = *(const float4*)&bias[tx * 4];
    #pragma unroll
    for (int mp = 0; mp < 4; mp++) {
        float2 f0 = upk2(acc[mp][0]), f1 = upk2(acc[mp][1]);
        float2 f2 = upk2(acc[mp][2]), f3 = upk2(acc[mp][3]);
        int m = m0 + ty * 8 + 2 * mp;
        float4 r0 = make_float4(f0.x + bb.x, f1.x + bb.y, f2.x + bb.z, f3.x + bb.w);
        float4 r1 = make_float4(f0.y + bb.x, f1.y + bb.y, f2.y + bb.z, f3.y + bb.w);
        *(float4*)&O[(size_t)m * CC + tx * 4] = r0;
        *(float4*)&O[(size_t)(m + 1) * CC + tx * 4] = r1;
    }
}

// ---------------------------------------------------------------------------
// Fused kNN + GEMM kernel. Roles interleaved 8:5 so both kinds co-reside
// on each SM (knn = ALU/issue pipe, gemm = FMA pipe -> overlap).
// ---------------------------------------------------------------------------
__global__ __launch_bounds__(256, 3) void fused_kg_kernel(
    const float* __restrict__ coord, const float* __restrict__ pcd,
    const float* __restrict__ bq, const float* __restrict__ bk,
    const float* __restrict__ bv) {
    extern __shared__ char smraw[];
    const int grp = blockIdx.x / 13;      // 0..255
    const int r   = blockIdx.x % 13;
    if (r < 8) {
        knn_body(smraw, coord, grp * 8 + r);           // 2048 knn blocks
    } else {
        int gid = grp * 5 + (r - 8);                   // 0..1279
        int y = gid >> 8, mblk = gid & 255;
        const ull* Wd = g_Wd + (size_t)y * CC * CC;
        if (y == 0)      gemm_body(smraw, pcd, Wd, bq, g_Q, mblk * MT);
        else if (y == 1) gemm_body(smraw, pcd, Wd, bv, g_V, mblk * MT);
        else {
            int i = y - 2;
            gemm_body(smraw, pcd, Wd, bk + i * CC,
                      g_KF + (size_t)i * BN * CC, mblk * MT);
        }
    }
}

// ---------------------------------------------------------------------------
// Kernel 2: attention via Kf gathers. One warp per point, 8 points/block.
// ---------------------------------------------------------------------------
__global__ __launch_bounds__(256, 6) void attn_kernel(float* __restrict__ out)
{
    __shared__ int   s_kn[APP][KT];
    __shared__ float s_raw[APP][HH][56];
    __shared__ float s_attn[APP][HH];

    const int t = threadIdx.x;
    const int lane = t & 31, w = t >> 5;
    const int g = lane & 7, kq = lane >> 3;
    const int b = blockIdx.x / (NN / APP);
    const int n0 = (blockIdx.x % (NN / APP)) * APP;
    const int gbase = b * NN;

    for (int idx = t; idx < APP * KT; idx += 256) {
        int p = idx / KT, j = idx % KT;
        s_kn[p][j] = g_knn[(size_t)(gbase + n0 + p) * KT + j];
    }
    __syncthreads();

    const int n = n0 + w;

    ulonglong2 qm[4];
    {
        const float* qrow = g_Q + (size_t)(gbase + n) * CC;
        #pragma unroll
        for (int m = 0; m < 4; m++)
            qm[m] = *(const ulonglong2*)&qrow[4 * g + 32 * m];
    }

    auto job_ext = [&](int jid) -> int {
        int i = (jid >= 36) ? 2 : (jid >= 18 ? 1 : 0);
        int r = jid - 18 * i;
        if (r < 16)  return i * BN + gbase + s_kn[w][i * KNB + r];
        if (r == 16) return i * BN + gbase + n;
        return SS * BN + i;
    };
    int je0 = job_ext(lane);
    int je1 = (lane < NJOB - 32) ? job_ext(32 + lane) : je0;

    #pragma unroll
    for (int ch = 0; ch < 14; ch++) {
        int jid = (ch < 8) ? (4 * ch + kq) : (32 + 4 * (ch - 8) + kq);
        int src = (ch < 8) ? (4 * ch + kq) : (4 * (ch - 8) + kq);
        int jext = __shfl_sync(FULLMASK, (ch < 8) ? je0 : je1, src);
        const float* kf = g_KF + (size_t)jext * CC;

        ull a0 = 0, a1 = 0, a2 = 0, a3 = 0;
        {
            ulonglong2 nb0 = *(const ulonglong2*)&kf[4 * g];
            ulonglong2 nb1 = *(const ulonglong2*)&kf[4 * g + 32];
            ulonglong2 nb2 = *(const ulonglong2*)&kf[4 * g + 64];
            ulonglong2 nb3 = *(const ulonglong2*)&kf[4 * g + 96];
            fma2(a0, nb0.x, qm[0].x); fma2(a0, nb0.y, qm[0].y);
            fma2(a1, nb1.x, qm[1].x); fma2(a1, nb1.y, qm[1].y);
            fma2(a2, nb2.x, qm[2].x); fma2(a2, nb2.y, qm[2].y);
            fma2(a3, nb3.x, qm[3].x); fma2(a3, nb3.y, qm[3].y);
        }
        float2 f0 = upk2(a0), f1 = upk2(a1), f2 = upk2(a2), f3 = upk2(a3);
        float s0 = f0.x + f0.y, s1 = f1.x + f1.y;
        float s2 = f2.x + f2.y, s3 = f3.x + f3.y;
        #pragma unroll
        for (int off = 1; off <= 4; off <<= 1) {
            s0 += __shfl_xor_sync(FULLMASK, s0, off);
            s1 += __shfl_xor_sync(FULLMASK, s1, off);
            s2 += __shfl_xor_sync(FULLMASK, s2, off);
            s3 += __shfl_xor_sync(FULLMASK, s3, off);
        }
        float val = (g == 0) ? s0 : (g == 1) ? s1 : (g == 2) ? s2 : s3;
        if (g < 4 && jid < NJOB) s_raw[w][g][jid] = val;
    }
    __syncthreads();

    if (t < APP * HH) {
        const int p = t >> 2, h = t & 3;
        const float inv = 0.17677669529663687f;   // 1/sqrt(32)
        float accA = 0.0f;
        #pragma unroll
        for (int i = 0; i < SS; i++) {
            const float* raw = &s_raw[p][h][i * 18];
            float corr = raw[17] - raw[16];        // q.bk - q.Kf'[n]
            float l[KNB];
            float mx = -1e30f;
            #pragma unroll
            for (int k = 0; k < KNB; k++) {
                l[k] = inv * (raw[k] + corr);
                mx = fmaxf(mx, l[k]);
            }
            float se = 0.0f, sl = 0.0f;
            #pragma unroll
            for (int k = 0; k < KNB; k++) {
                float e = __expf(l[k] - mx);
                se += e;
                sl = fmaf(e, l[k], sl);
            }
            accA += sl / se;
        }
        s_attn[p][h] = accA;
    }
    __syncthreads();

    {
        int p = t >> 5, c4 = t & 31;
        size_t nn = (size_t)gbase + n0 + p;
        float4 vv = *(const float4*)&g_V[nn * CC + 4 * c4];
        float a = s_attn[p][c4 >> 3];
        float4 rr = make_float4(a * vv.x, a * vv.y, a * vv.z, a * vv.w);
        *(float4*)&out[nn * CC + 4 * c4] = rr;
    }
}

// ---------------------------------------------------------------------------
extern "C" void kernel_launch(void* const* d_in, const int* in_sizes, int n_in,
                              void* d_out, int out_size) {
    (void)in_sizes; (void)n_in; (void)out_size;
    const float* pcd   = (const float*)d_in[0];
    const float* coord = (const float*)d_in[1];
    const float* Wq    = (const float*)d_in[3];
    const float* bq    = (const float*)d_in[4];
    const float* Wk    = (const float*)d_in[5];
    const float* bk    = (const float*)d_in[6];
    const float* Wv    = (const float*)d_in[7];
    const float* bv    = (const float*)d_in[8];
    float* out = (float*)d_out;

    constexpr int SMEMB = (int)sizeof(KnnS) > (int)sizeof(GemmS)
                        ? (int)sizeof(KnnS) : (int)sizeof(GemmS);
    static_assert(SMEMB <= 60 * 1024, "smem");
    cudaFuncSetAttribute(fused_kg_kernel,
                         cudaFuncAttributeMaxDynamicSharedMemorySize, SMEMB);

    prep_kernel<<<(5 * CC * CC + SS * CC + 255) / 256, 256>>>(Wq, Wv, Wk, bk);
    fused_kg_kernel<<<13 * 256, 256, SMEMB>>>(coord, pcd, bq, bk, bv);
    attn_kernel<<<BN / APP, 256>>>(out);
}

// round 10
// speedup vs baseline: 1.1808x; 1.1808x over previous
#include <cuda_runtime.h>

#define BB 8
#define NN 2048
#define BN (BB * NN)
#define CC 128
#define HH 4
#define DD 32
#define SS 3
#define KNB 16
#define KT 48
#define MT 64          // GEMM m-tile
#define APP 8          // points per attn block (1 warp each)
#define NJOB 54        // 48 nbr + 3 own + 3 bk
#define CAP 256        // knn candidate capacity per warp

#define FULLMASK 0xffffffffu
typedef unsigned long long ull;

__device__ int   g_knn[BN * KT];
__device__ float g_Q[BN * CC];
__device__ float g_V[BN * CC];
__device__ float g_KF[(SS * BN + SS) * CC];   // + SS rows of bk at the tail

// ---- f32x2 packed-FMA helpers (full fp32 precision, 2 FMA / instr) --------
__device__ __forceinline__ ull pk2(float lo, float hi) {
    ull r; asm("mov.b64 %0, {%1,%2};" : "=l"(r) : "f"(lo), "f"(hi)); return r;
}
__device__ __forceinline__ void fma2(ull& d, ull a, ull b) {
    asm("fma.rn.f32x2 %0, %1, %2, %0;" : "+l"(d) : "l"(a), "l"(b));
}
__device__ __forceinline__ float2 upk2(ull v) {
    float2 f; asm("mov.b64 {%0,%1}, %2;" : "=f"(f.x), "=f"(f.y) : "l"(v)); return f;
}

// ---------------------------------------------------------------------------
// Shared-memory layouts for the fused kernel (union via dynamic smem)
// ---------------------------------------------------------------------------
struct KnnS {
    float4 c4[NN];          // (x, y, z, |p|^2)       32 KB
    ull    cand[8][CAP];    // compacted candidates   16 KB
    ull    buf[8][64];      // sort buffer             4 KB
};
struct GemmS { float XsT[CC][72]; };                // 36.9 KB

// ---------------------------------------------------------------------------
// kNN body: exact top-48 per query (one warp per query, 8 queries/block).
// ---------------------------------------------------------------------------
__device__ __forceinline__ void knn_body(char* smraw, const float* __restrict__ coord,
                                         int bx) {
    KnnS* K = (KnnS*)smraw;
    const int t = threadIdx.x;
    const int lane = t & 31, w = t >> 5;
    const int b = bx >> 8;                 // 256 blocks per batch
    const int n0 = (bx & 255) * 8;
    const float* cb = coord + (size_t)b * NN * 3;

    for (int j = t; j < NN; j += 256) {
        float x = cb[3 * j], y = cb[3 * j + 1], z = cb[3 * j + 2];
        K->c4[j] = make_float4(x, y, z, fmaf(x, x, fmaf(y, y, z * z)));
    }
    __syncthreads();

    const int n = n0 + w;
    const float4 o = K->c4[n];

    unsigned kkey[64];
    unsigned m1 = 0xffffffffu, m2 = 0xffffffffu;
    #pragma unroll
    for (int s = 0; s < 64; s++) {
        int j = lane + (s << 5);
        float4 c = K->c4[j];
        float dot = fmaf(o.x, c.x, fmaf(o.y, c.y, o.z * c.z));
        float d = fmaf(-2.0f, dot, o.w + c.w);         // matches reference formula
        unsigned u = __float_as_uint(d);
        u = u ^ (unsigned)(((int)u >> 31) | 0x80000000);  // monotone total order
        kkey[s] = u;
        if (u < m1) { m2 = m1; m1 = u; } else if (u < m2) { m2 = u; }
    }

    unsigned lo = __reduce_min_sync(FULLMASK, m1);
    unsigned hi = __reduce_max_sync(FULLMASK, m2);    // >= 64 keys <= hi

    // ---- compact all keys <= hi via prefix scan (lane-major order) ----
    int cnt = 0;
    #pragma unroll
    for (int s = 0; s < 64; s++) cnt += (kkey[s] <= hi) ? 1 : 0;
    int pre = cnt;
    #pragma unroll
    for (int off = 1; off < 32; off <<= 1) {
        int v = __shfl_up_sync(FULLMASK, pre, off);
        pre += (lane >= off) ? v : 0;
    }
    const int total = __shfl_sync(FULLMASK, pre, 31);
    if (total <= CAP) {
        int pos = pre - cnt;
        #pragma unroll
        for (int s = 0; s < 64; s++) {
            if (kkey[s] <= hi)
                K->cand[w][pos++] = ((ull)kkey[s] << 32) | (unsigned)(lane + (s << 5));
        }
    }
    __syncwarp();

    unsigned T;
    if (total <= CAP) {
        // ---- binary search over <= 8 candidates per lane ----
        unsigned ck[8];
        #pragma unroll
        for (int sl = 0; sl < 8; sl++) {
            int p = lane + (sl << 5);
            ck[sl] = (p < total) ? (unsigned)(K->cand[w][p] >> 32) : 0xffffffffu;
        }
        for (;;) {
            if (lo >= hi) { T = lo; break; }
            unsigned mid = lo + ((hi - lo) >> 1);
            unsigned c = 0;
            #pragma unroll
            for (int sl = 0; sl < 8; sl++) c += (ck[sl] <= mid) ? 1u : 0u;
            c = __reduce_add_sync(FULLMASK, c);
            if (c == KT) { T = mid; break; }
            if (c > KT) hi = mid; else lo = mid + 1;
        }
        // ---- collect <= T into buf via prefix scan ----
        K->buf[w][lane] = ~0ull;
        K->buf[w][lane + 32] = ~0ull;
        __syncwarp();
        int c2 = 0;
        #pragma unroll
        for (int sl = 0; sl < 8; sl++) c2 += (ck[sl] <= T) ? 1 : 0;
        int p2 = c2;
        #pragma unroll
        for (int off = 1; off < 32; off <<= 1) {
            int v = __shfl_up_sync(FULLMASK, p2, off);
            p2 += (lane >= off) ? v : 0;
        }
        int pos2 = p2 - c2;
        #pragma unroll
        for (int sl = 0; sl < 8; sl++) {
            if (ck[sl] <= T) {
                if (pos2 < 64) K->buf[w][pos2] = K->cand[w][lane + (sl << 5)];
                pos2++;
            }
        }
    } else {
        // ---- rare fallback: full 64-key search + ballot collect ----
        for (;;) {
            if (lo >= hi) { T = lo; break; }
            unsigned mid = lo + ((hi - lo) >> 1);
            unsigned c = 0;
            #pragma unroll
            for (int s = 0; s < 64; s++) c += (kkey[s] <= mid) ? 1u : 0u;
            c = __reduce_add_sync(FULLMASK, c);
            if (c == KT) { T = mid; break; }
            if (c > KT) hi = mid; else lo = mid + 1;
        }
        K->buf[w][lane] = ~0ull;
        K->buf[w][lane + 32] = ~0ull;
        __syncwarp();
        int bs = 0;
        #pragma unroll
        for (int s = 0; s < 64; s++) {
            bool q = (kkey[s] <= T);
            unsigned mm = __ballot_sync(FULLMASK, q);
            if (q) {
                int pos = bs + __popc(mm & ((1u << lane) - 1u));
                if (pos < 64)
                    K->buf[w][pos] = ((ull)kkey[s] << 32) | (unsigned)(lane + (s << 5));
            }
            bs += __popc(mm);
        }
    }
    __syncwarp();

    // ---- bitonic sort of 64 u64 keys, 2 per lane -> exact (dist, idx) order
    ull v0 = K->buf[w][lane];
    ull v1 = K->buf[w][lane + 32];
    #pragma unroll
    for (int k2 = 2; k2 <= 64; k2 <<= 1) {
        #pragma unroll
        for (int j2 = k2 >> 1; j2 > 0; j2 >>= 1) {
            if (j2 == 32) {
                ull a = v0 < v1 ? v0 : v1;
                ull bm = v0 < v1 ? v1 : v0;
                v0 = a; v1 = bm;
            } else {
                bool low = ((lane & j2) == 0);
                bool up0 = ((lane & k2) == 0);
                bool up1 = (((lane + 32) & k2) == 0);
                ull o0 = __shfl_xor_sync(FULLMASK, v0, j2);
                ull o1 = __shfl_xor_sync(FULLMASK, v1, j2);
                bool t0 = (low == up0);
                bool t1 = (low == up1);
                v0 = t0 ? (v0 < o0 ? v0 : o0) : (v0 > o0 ? v0 : o0);
                v1 = t1 ? (v1 < o1 ? v1 : o1) : (v1 > o1 ? v1 : o1);
            }
        }
    }

    int* outp = g_knn + ((size_t)b * NN + n) * KT;
    outp[lane] = (int)(v0 & 0xffffffffu);
    if (lane < KT - 32) outp[32 + lane] = (int)(v1 & 0xffffffffu);
}

// ---------------------------------------------------------------------------
// Register-tiled GEMM body (R7 form): O[m0..m0+64][0..128) = A @ W + bias
// Weight fetch = one LDG.128/warp/k (512B -> 4 L1 wavefronts) + reg splats.
// ---------------------------------------------------------------------------
__device__ __forceinline__ void gemm_body(char* smraw,
                                          const float* __restrict__ A,
                                          const float* __restrict__ W,
                                          const float* __restrict__ bias,
                                          float* __restrict__ O, int m0) {
    GemmS* G = (GemmS*)smraw;
    const int t = threadIdx.x;
    const int tx = t & 31, ty = t >> 5;

    #pragma unroll
    for (int s = t; s < MT * CC / 4; s += 256) {
        int m = s >> 5, k4 = s & 31;
        float4 v = *(const float4*)&A[(size_t)(m0 + m) * CC + 4 * k4];
        G->XsT[4 * k4 + 0][m] = v.x;
        G->XsT[4 * k4 + 1][m] = v.y;
        G->XsT[4 * k4 + 2][m] = v.z;
        G->XsT[4 * k4 + 3][m] = v.w;
    }
    __syncthreads();

    ull acc[4][4];
    #pragma unroll
    for (int mp = 0; mp < 4; mp++)
        #pragma unroll
        for (int c = 0; c < 4; c++) acc[mp][c] = 0;

    #pragma unroll 8
    for (int k = 0; k < CC; k++) {
        float4 wv = __ldg(&((const float4*)W)[k * 32 + tx]);
        ull w0 = pk2(wv.x, wv.x), w1 = pk2(wv.y, wv.y);
        ull w2 = pk2(wv.z, wv.z), w3 = pk2(wv.w, wv.w);
        ulonglong2 xa = *(const ulonglong2*)&G->XsT[k][ty * 8];
        ulonglong2 xb = *(const ulonglong2*)&G->XsT[k][ty * 8 + 4];
        fma2(acc[0][0], xa.x, w0); fma2(acc[0][1], xa.x, w1);
        fma2(acc[0][2], xa.x, w2); fma2(acc[0][3], xa.x, w3);
        fma2(acc[1][0], xa.y, w0); fma2(acc[1][1], xa.y, w1);
        fma2(acc[1][2], xa.y, w2); fma2(acc[1][3], xa.y, w3);
        fma2(acc[2][0], xb.x, w0); fma2(acc[2][1], xb.x, w1);
        fma2(acc[2][2], xb.x, w2); fma2(acc[2][3], xb.x, w3);
        fma2(acc[3][0], xb.y, w0); fma2(acc[3][1], xb.y, w1);
        fma2(acc[3][2], xb.y, w2); fma2(acc[3][3], xb.y, w3);
    }

    float4 bb = *(const float4*)&bias[tx * 4];
    #pragma unroll
    for (int mp = 0; mp < 4; mp++) {
        float2 f0 = upk2(acc[mp][0]), f1 = upk2(acc[mp][1]);
        float2 f2 = upk2(acc[mp][2]), f3 = upk2(acc[mp][3]);
        int m = m0 + ty * 8 + 2 * mp;
        float4 r0 = make_float4(f0.x + bb.x, f1.x + bb.y, f2.x + bb.z, f3.x + bb.w);
        float4 r1 = make_float4(f0.y + bb.x, f1.y + bb.y, f2.y + bb.z, f3.y + bb.w);
        *(float4*)&O[(size_t)m * CC + tx * 4] = r0;
        *(float4*)&O[(size_t)(m + 1) * CC + tx * 4] = r1;
    }
}

// ---------------------------------------------------------------------------
// Fused kNN + GEMM kernel. Roles interleaved 8:5 so both kinds co-reside.
// ---------------------------------------------------------------------------
__global__ __launch_bounds__(256, 3) void fused_kg_kernel(
    const float* __restrict__ coord, const float* __restrict__ pcd,
    const float* __restrict__ Wq, const float* __restrict__ bq,
    const float* __restrict__ Wk, const float* __restrict__ bk,
    const float* __restrict__ Wv, const float* __restrict__ bv) {
    extern __shared__ char smraw[];
    const int grp = blockIdx.x / 13;      // 0..255
    const int r   = blockIdx.x % 13;
    if (r < 8) {
        knn_body(smraw, coord, grp * 8 + r);           // 2048 knn blocks
    } else {
        int gid = grp * 5 + (r - 8);                   // 0..1279
        int y = gid >> 8, mblk = gid & 255;
        if (y == 0)      gemm_body(smraw, pcd, Wq, bq, g_Q, mblk * MT);
        else if (y == 1) gemm_body(smraw, pcd, Wv, bv, g_V, mblk * MT);
        else {
            int i = y - 2;
            if (mblk == 0 && threadIdx.x < CC)         // bk rows at g_KF tail
                g_KF[(size_t)(SS * BN + i) * CC + threadIdx.x] = bk[i * CC + threadIdx.x];
            gemm_body(smraw, pcd, Wk + i * CC * CC, bk + i * CC,
                      g_KF + (size_t)i * BN * CC, mblk * MT);
        }
    }
}

// ---------------------------------------------------------------------------
// Kernel 2: attention via Kf gathers. One warp per point, 8 points/block.
// ---------------------------------------------------------------------------
__global__ __launch_bounds__(256, 6) void attn_kernel(float* __restrict__ out)
{
    __shared__ int   s_kn[APP][KT];
    __shared__ float s_raw[APP][HH][56];
    __shared__ float s_attn[APP][HH];

    const int t = threadIdx.x;
    const int lane = t & 31, w = t >> 5;
    const int g = lane & 7, kq = lane >> 3;
    const int b = blockIdx.x / (NN / APP);
    const int n0 = (blockIdx.x % (NN / APP)) * APP;
    const int gbase = b * NN;

    for (int idx = t; idx < APP * KT; idx += 256) {
        int p = idx / KT, j = idx % KT;
        s_kn[p][j] = g_knn[(size_t)(gbase + n0 + p) * KT + j];
    }
    __syncthreads();

    const int n = n0 + w;

    ulonglong2 qm[4];
    {
        const float* qrow = g_Q + (size_t)(gbase + n) * CC;
        #pragma unroll
        for (int m = 0; m < 4; m++)
            qm[m] = *(const ulonglong2*)&qrow[4 * g + 32 * m];
    }

    auto job_ext = [&](int jid) -> int {
        int i = (jid >= 36) ? 2 : (jid >= 18 ? 1 : 0);
        int r = jid - 18 * i;
        if (r < 16)  return i * BN + gbase + s_kn[w][i * KNB + r];
        if (r == 16) return i * BN + gbase + n;
        return SS * BN + i;
    };
    int je0 = job_ext(lane);
    int je1 = (lane < NJOB - 32) ? job_ext(32 + lane) : je0;

    #pragma unroll
    for (int ch = 0; ch < 14; ch++) {
        int jid = (ch < 8) ? (4 * ch + kq) : (32 + 4 * (ch - 8) + kq);
        int src = (ch < 8) ? (4 * ch + kq) : (4 * (ch - 8) + kq);
        int jext = __shfl_sync(FULLMASK, (ch < 8) ? je0 : je1, src);
        const float* kf = g_KF + (size_t)jext * CC;

        ull a0 = 0, a1 = 0, a2 = 0, a3 = 0;
        {
            ulonglong2 nb0 = *(const ulonglong2*)&kf[4 * g];
            ulonglong2 nb1 = *(const ulonglong2*)&kf[4 * g + 32];
            ulonglong2 nb2 = *(const ulonglong2*)&kf[4 * g + 64];
            ulonglong2 nb3 = *(const ulonglong2*)&kf[4 * g + 96];
            fma2(a0, nb0.x, qm[0].x); fma2(a0, nb0.y, qm[0].y);
            fma2(a1, nb1.x, qm[1].x); fma2(a1, nb1.y, qm[1].y);
            fma2(a2, nb2.x, qm[2].x); fma2(a2, nb2.y, qm[2].y);
            fma2(a3, nb3.x, qm[3].x); fma2(a3, nb3.y, qm[3].y);
        }
        float2 f0 = upk2(a0), f1 = upk2(a1), f2 = upk2(a2), f3 = upk2(a3);
        float s0 = f0.x + f0.y, s1 = f1.x + f1.y;
        float s2 = f2.x + f2.y, s3 = f3.x + f3.y;
        #pragma unroll
        for (int off = 1; off <= 4; off <<= 1) {
            s0 += __shfl_xor_sync(FULLMASK, s0, off);
            s1 += __shfl_xor_sync(FULLMASK, s1, off);
            s2 += __shfl_xor_sync(FULLMASK, s2, off);
            s3 += __shfl_xor_sync(FULLMASK, s3, off);
        }
        float val = (g == 0) ? s0 : (g == 1) ? s1 : (g == 2) ? s2 : s3;
        if (g < 4 && jid < NJOB) s_raw[w][g][jid] = val;
    }
    __syncthreads();

    if (t < APP * HH) {
        const int p = t >> 2, h = t & 3;
        const float inv = 0.17677669529663687f;   // 1/sqrt(32)
        float accA = 0.0f;
        #pragma unroll
        for (int i = 0; i < SS; i++) {
            const float* raw = &s_raw[p][h][i * 18];
            float corr = raw[17] - raw[16];        // q.bk - q.Kf'[n]
            float l[KNB];
            float mx = -1e30f;
            #pragma unroll
            for (int k = 0; k < KNB; k++) {
                l[k] = inv * (raw[k] + corr);
                mx = fmaxf(mx, l[k]);
            }
            float se = 0.0f, sl = 0.0f;
            #pragma unroll
            for (int k = 0; k < KNB; k++) {
                float e = __expf(l[k] - mx);
                se += e;
                sl = fmaf(e, l[k], sl);
            }
            accA += sl / se;
        }
        s_attn[p][h] = accA;
    }
    __syncthreads();

    {
        int p = t >> 5, c4 = t & 31;
        size_t nn = (size_t)gbase + n0 + p;
        float4 vv = *(const float4*)&g_V[nn * CC + 4 * c4];
        float a = s_attn[p][c4 >> 3];
        float4 rr = make_float4(a * vv.x, a * vv.y, a * vv.z, a * vv.w);
        *(float4*)&out[nn * CC + 4 * c4] = rr;
    }
}

// ---------------------------------------------------------------------------
extern "C" void kernel_launch(void* const* d_in, const int* in_sizes, int n_in,
                              void* d_out, int out_size) {
    (void)in_sizes; (void)n_in; (void)out_size;
    const float* pcd   = (const float*)d_in[0];
    const float* coord = (const float*)d_in[1];
    const float* Wq    = (const float*)d_in[3];
    const float* bq    = (const float*)d_in[4];
    const float* Wk    = (const float*)d_in[5];
    const float* bk    = (const float*)d_in[6];
    const float* Wv    = (const float*)d_in[7];
    const float* bv    = (const float*)d_in[8];
    float* out = (float*)d_out;

    constexpr int SMEMB = (int)sizeof(KnnS) > (int)sizeof(GemmS)
                        ? (int)sizeof(KnnS) : (int)sizeof(GemmS);
    static_assert(SMEMB <= 60 * 1024, "smem");
    cudaFuncSetAttribute(fused_kg_kernel,
                         cudaFuncAttributeMaxDynamicSharedMemorySize, SMEMB);

    fused_kg_kernel<<<13 * 256, 256, SMEMB>>>(coord, pcd, Wq, bq, Wk, bk, Wv, bv);
    attn_kernel<<<BN / APP, 256>>>(out);
}

// round 11
// speedup vs baseline: 1.2728x; 1.0780x over previous
#include <cuda_runtime.h>

#define BB 8
#define NN 2048
#define BN (BB * NN)
#define CC 128
#define HH 4
#define DD 32
#define SS 3
#define KNB 16
#define KT 48
#define MT 64          // GEMM m-tile
#define APP 8          // points per attn block (1 warp each)
#define NJOB 54        // 48 nbr + 3 own + 3 bk
#define CAP 256        // knn candidate capacity per warp

#define FULLMASK 0xffffffffu
typedef unsigned long long ull;

__device__ int   g_knn[BN * KT];
__device__ float g_Q[BN * CC];
__device__ float g_V[BN * CC];
__device__ float g_KF[(SS * BN + SS) * CC];   // + SS rows of bk at the tail

// ---- f32x2 packed-FMA helpers (full fp32 precision, 2 FMA / instr) --------
__device__ __forceinline__ ull pk2(float lo, float hi) {
    ull r; asm("mov.b64 %0, {%1,%2};" : "=l"(r) : "f"(lo), "f"(hi)); return r;
}
__device__ __forceinline__ void fma2(ull& d, ull a, ull b) {
    asm("fma.rn.f32x2 %0, %1, %2, %0;" : "+l"(d) : "l"(a), "l"(b));
}
__device__ __forceinline__ float2 upk2(ull v) {
    float2 f; asm("mov.b64 {%0,%1}, %2;" : "=f"(f.x), "=f"(f.y) : "l"(v)); return f;
}

// ---------------------------------------------------------------------------
// Kernel 1: exact top-48 kNN per query (R7 body: ballot compaction, pruned
// binary search).  One warp per query, 8 queries/block.
// ---------------------------------------------------------------------------
struct KnnS {
    float4 c4[NN];          // (x, y, z, |p|^2)       32 KB
    ull    cand[8][CAP];    // compacted candidates   16 KB
    ull    buf[8][64];      // sort buffer             4 KB
};

__global__ __launch_bounds__(256, 3) void knn_kernel(const float* __restrict__ coord) {
    extern __shared__ char smraw[];
    KnnS* K = (KnnS*)smraw;
    const int t = threadIdx.x;
    const int lane = t & 31, w = t >> 5;
    const int b = blockIdx.x >> 8;                 // 256 blocks per batch
    const int n0 = (blockIdx.x & 255) * 8;
    const float* cb = coord + (size_t)b * NN * 3;

    for (int j = t; j < NN; j += 256) {
        float x = cb[3 * j], y = cb[3 * j + 1], z = cb[3 * j + 2];
        K->c4[j] = make_float4(x, y, z, fmaf(x, x, fmaf(y, y, z * z)));
    }
    __syncthreads();

    const int n = n0 + w;
    const float4 o = K->c4[n];

    unsigned kkey[64];
    unsigned m1 = 0xffffffffu, m2 = 0xffffffffu;
    #pragma unroll
    for (int s = 0; s < 64; s++) {
        int j = lane + (s << 5);
        float4 c = K->c4[j];
        float dot = fmaf(o.x, c.x, fmaf(o.y, c.y, o.z * c.z));
        float d = fmaf(-2.0f, dot, o.w + c.w);         // matches reference formula
        unsigned u = __float_as_uint(d);
        u = (u & 0x80000000u) ? ~u : (u | 0x80000000u);  // monotone total order
        kkey[s] = u;
        if (u < m1) { m2 = m1; m1 = u; } else if (u < m2) { m2 = u; }
    }

    unsigned lo = __reduce_min_sync(FULLMASK, m1);
    unsigned hi = __reduce_max_sync(FULLMASK, m2);    // >= 64 keys <= hi

    // ---- compact all keys <= hi into smem (ballot/popc; count in base) ----
    int base = 0;
    #pragma unroll
    for (int s = 0; s < 64; s++) {
        bool q = (kkey[s] <= hi);
        unsigned mm = __ballot_sync(FULLMASK, q);
        if (q) {
            int pos = base + __popc(mm & ((1u << lane) - 1u));
            if (pos < CAP)
                K->cand[w][pos] = ((ull)kkey[s] << 32) | (unsigned)(lane + (s << 5));
        }
        base += __popc(mm);
    }
    __syncwarp();

    unsigned T;
    if (base <= CAP) {
        // ---- binary search over <= 8 candidates per lane ----
        unsigned ck[8];
        #pragma unroll
        for (int sl = 0; sl < 8; sl++) {
            int p = lane + (sl << 5);
            ck[sl] = (p < base) ? (unsigned)(K->cand[w][p] >> 32) : 0xffffffffu;
        }
        for (;;) {
            if (lo >= hi) { T = lo; break; }
            unsigned mid = lo + ((hi - lo) >> 1);
            unsigned c = 0;
            #pragma unroll
            for (int sl = 0; sl < 8; sl++) c += (ck[sl] <= mid) ? 1u : 0u;
            c = __reduce_add_sync(FULLMASK, c);
            if (c == KT) { T = mid; break; }     // exactly the 48 smallest
            if (c > KT) hi = mid; else lo = mid + 1;
        }
        // ---- collect <= T into buf (ballot/popc) ----
        K->buf[w][lane] = ~0ull;
        K->buf[w][lane + 32] = ~0ull;
        __syncwarp();
        int bs = 0;
        #pragma unroll
        for (int sl = 0; sl < 8; sl++) {
            int p = lane + (sl << 5);
            bool q = (ck[sl] <= T);
            unsigned mm = __ballot_sync(FULLMASK, q);
            if (q) {
                int pos = bs + __popc(mm & ((1u << lane) - 1u));
                if (pos < 64) K->buf[w][pos] = K->cand[w][p];
            }
            bs += __popc(mm);
        }
    } else {
        // ---- rare fallback: full 64-key search + ballot collect ----
        for (;;) {
            if (lo >= hi) { T = lo; break; }
            unsigned mid = lo + ((hi - lo) >> 1);
            unsigned c = 0;
            #pragma unroll
            for (int s = 0; s < 64; s++) c += (kkey[s] <= mid) ? 1u : 0u;
            c = __reduce_add_sync(FULLMASK, c);
            if (c == KT) { T = mid; break; }
            if (c > KT) hi = mid; else lo = mid + 1;
        }
        K->buf[w][lane] = ~0ull;
        K->buf[w][lane + 32] = ~0ull;
        __syncwarp();
        int bs = 0;
        #pragma unroll
        for (int s = 0; s < 64; s++) {
            bool q = (kkey[s] <= T);
            unsigned mm = __ballot_sync(FULLMASK, q);
            if (q) {
                int pos = bs + __popc(mm & ((1u << lane) - 1u));
                if (pos < 64)
                    K->buf[w][pos] = ((ull)kkey[s] << 32) | (unsigned)(lane + (s << 5));
            }
            bs += __popc(mm);
        }
    }
    __syncwarp();

    // ---- bitonic sort of 64 u64 keys, 2 per lane -> exact (dist, idx) order
    ull v0 = K->buf[w][lane];
    ull v1 = K->buf[w][lane + 32];
    #pragma unroll
    for (int k2 = 2; k2 <= 64; k2 <<= 1) {
        #pragma unroll
        for (int j2 = k2 >> 1; j2 > 0; j2 >>= 1) {
            if (j2 == 32) {
                ull a = v0 < v1 ? v0 : v1;
                ull bm = v0 < v1 ? v1 : v0;
                v0 = a; v1 = bm;
            } else {
                bool low = ((lane & j2) == 0);
                bool up0 = ((lane & k2) == 0);
                bool up1 = (((lane + 32) & k2) == 0);
                ull o0 = __shfl_xor_sync(FULLMASK, v0, j2);
                ull o1 = __shfl_xor_sync(FULLMASK, v1, j2);
                bool t0 = (low == up0);
                bool t1 = (low == up1);
                v0 = t0 ? (v0 < o0 ? v0 : o0) : (v0 > o0 ? v0 : o0);
                v1 = t1 ? (v1 < o1 ? v1 : o1) : (v1 > o1 ? v1 : o1);
            }
        }
    }

    int* outp = g_knn + ((size_t)b * NN + n) * KT;
    outp[lane] = (int)(v0 & 0xffffffffu);
    if (lane < KT - 32) outp[32 + lane] = (int)(v1 & 0xffffffffu);
}

// ---------------------------------------------------------------------------
// Kernel 2: register-tiled GEMM (R7 body, standalone).
// O[m0..m0+64][0..128) = A @ W + bias ; weight fetch = 1 LDG.128/warp/k.
// ---------------------------------------------------------------------------
__global__ __launch_bounds__(256, 3) void gemm_kernel(
    const float* __restrict__ pcd,
    const float* __restrict__ Wq, const float* __restrict__ bq,
    const float* __restrict__ Wk, const float* __restrict__ bk,
    const float* __restrict__ Wv, const float* __restrict__ bv) {
    __shared__ float XsT[CC][72];
    const int t = threadIdx.x;
    const int tx = t & 31, ty = t >> 5;
    const int y = blockIdx.y;
    const int m0 = blockIdx.x * MT;

    const float* W;
    const float* bias;
    float* O;
    if (y == 0)      { W = Wq; bias = bq; O = g_Q; }
    else if (y == 1) { W = Wv; bias = bv; O = g_V; }
    else {
        int i = y - 2;
        W = Wk + i * CC * CC; bias = bk + i * CC;
        O = g_KF + (size_t)i * BN * CC;
        if (blockIdx.x == 0 && t < CC)             // bk rows at g_KF tail
            g_KF[(size_t)(SS * BN + i) * CC + t] = bk[i * CC + t];
    }

    #pragma unroll
    for (int s = t; s < MT * CC / 4; s += 256) {
        int m = s >> 5, k4 = s & 31;
        float4 v = *(const float4*)&pcd[(size_t)(m0 + m) * CC + 4 * k4];
        XsT[4 * k4 + 0][m] = v.x;
        XsT[4 * k4 + 1][m] = v.y;
        XsT[4 * k4 + 2][m] = v.z;
        XsT[4 * k4 + 3][m] = v.w;
    }
    __syncthreads();

    ull acc[4][4];
    #pragma unroll
    for (int mp = 0; mp < 4; mp++)
        #pragma unroll
        for (int c = 0; c < 4; c++) acc[mp][c] = 0;

    #pragma unroll 8
    for (int k = 0; k < CC; k++) {
        float4 wv = __ldg(&((const float4*)W)[k * 32 + tx]);
        ull w0 = pk2(wv.x, wv.x), w1 = pk2(wv.y, wv.y);
        ull w2 = pk2(wv.z, wv.z), w3 = pk2(wv.w, wv.w);
        ulonglong2 xa = *(const ulonglong2*)&XsT[k][ty * 8];
        ulonglong2 xb = *(const ulonglong2*)&XsT[k][ty * 8 + 4];
        fma2(acc[0][0], xa.x, w0); fma2(acc[0][1], xa.x, w1);
        fma2(acc[0][2], xa.x, w2); fma2(acc[0][3], xa.x, w3);
        fma2(acc[1][0], xa.y, w0); fma2(acc[1][1], xa.y, w1);
        fma2(acc[1][2], xa.y, w2); fma2(acc[1][3], xa.y, w3);
        fma2(acc[2][0], xb.x, w0); fma2(acc[2][1], xb.x, w1);
        fma2(acc[2][2], xb.x, w2); fma2(acc[2][3], xb.x, w3);
        fma2(acc[3][0], xb.y, w0); fma2(acc[3][1], xb.y, w1);
        fma2(acc[3][2], xb.y, w2); fma2(acc[3][3], xb.y, w3);
    }

    float4 bb = *(const float4*)&bias[tx * 4];
    #pragma unroll
    for (int mp = 0; mp < 4; mp++) {
        float2 f0 = upk2(acc[mp][0]), f1 = upk2(acc[mp][1]);
        float2 f2 = upk2(acc[mp][2]), f3 = upk2(acc[mp][3]);
        int m = m0 + ty * 8 + 2 * mp;
        float4 r0 = make_float4(f0.x + bb.x, f1.x + bb.y, f2.x + bb.z, f3.x + bb.w);
        float4 r1 = make_float4(f0.y + bb.x, f1.y + bb.y, f2.y + bb.z, f3.y + bb.w);
        *(float4*)&O[(size_t)m * CC + tx * 4] = r0;
        *(float4*)&O[(size_t)(m + 1) * CC + tx * 4] = r1;
    }
}

// ---------------------------------------------------------------------------
// Kernel 3: attention via Kf gathers. One warp per point, 8 points/block.
// ---------------------------------------------------------------------------
__global__ __launch_bounds__(256, 6) void attn_kernel(float* __restrict__ out)
{
    __shared__ int   s_kn[APP][KT];
    __shared__ float s_raw[APP][HH][56];
    __shared__ float s_attn[APP][HH];

    const int t = threadIdx.x;
    const int lane = t & 31, w = t >> 5;
    const int g = lane & 7, kq = lane >> 3;
    const int b = blockIdx.x / (NN / APP);
    const int n0 = (blockIdx.x % (NN / APP)) * APP;
    const int gbase = b * NN;

    for (int idx = t; idx < APP * KT; idx += 256) {
        int p = idx / KT, j = idx % KT;
        s_kn[p][j] = g_knn[(size_t)(gbase + n0 + p) * KT + j];
    }
    __syncthreads();

    const int n = n0 + w;

    ulonglong2 qm[4];
    {
        const float* qrow = g_Q + (size_t)(gbase + n) * CC;
        #pragma unroll
        for (int m = 0; m < 4; m++)
            qm[m] = *(const ulonglong2*)&qrow[4 * g + 32 * m];
    }

    auto job_ext = [&](int jid) -> int {
        int i = (jid >= 36) ? 2 : (jid >= 18 ? 1 : 0);
        int r = jid - 18 * i;
        if (r < 16)  return i * BN + gbase + s_kn[w][i * KNB + r];
        if (r == 16) return i * BN + gbase + n;
        return SS * BN + i;
    };
    int je0 = job_ext(lane);
    int je1 = (lane < NJOB - 32) ? job_ext(32 + lane) : je0;

    #pragma unroll
    for (int ch = 0; ch < 14; ch++) {
        int jid = (ch < 8) ? (4 * ch + kq) : (32 + 4 * (ch - 8) + kq);
        int src = (ch < 8) ? (4 * ch + kq) : (4 * (ch - 8) + kq);
        int jext = __shfl_sync(FULLMASK, (ch < 8) ? je0 : je1, src);
        const float* kf = g_KF + (size_t)jext * CC;

        ull a0 = 0, a1 = 0, a2 = 0, a3 = 0;
        {
            ulonglong2 nb0 = *(const ulonglong2*)&kf[4 * g];
            ulonglong2 nb1 = *(const ulonglong2*)&kf[4 * g + 32];
            ulonglong2 nb2 = *(const ulonglong2*)&kf[4 * g + 64];
            ulonglong2 nb3 = *(const ulonglong2*)&kf[4 * g + 96];
            fma2(a0, nb0.x, qm[0].x); fma2(a0, nb0.y, qm[0].y);
            fma2(a1, nb1.x, qm[1].x); fma2(a1, nb1.y, qm[1].y);
            fma2(a2, nb2.x, qm[2].x); fma2(a2, nb2.y, qm[2].y);
            fma2(a3, nb3.x, qm[3].x); fma2(a3, nb3.y, qm[3].y);
        }
        float2 f0 = upk2(a0), f1 = upk2(a1), f2 = upk2(a2), f3 = upk2(a3);
        float s0 = f0.x + f0.y, s1 = f1.x + f1.y;
        float s2 = f2.x + f2.y, s3 = f3.x + f3.y;
        #pragma unroll
        for (int off = 1; off <= 4; off <<= 1) {
            s0 += __shfl_xor_sync(FULLMASK, s0, off);
            s1 += __shfl_xor_sync(FULLMASK, s1, off);
            s2 += __shfl_xor_sync(FULLMASK, s2, off);
            s3 += __shfl_xor_sync(FULLMASK, s3, off);
        }
        float val = (g == 0) ? s0 : (g == 1) ? s1 : (g == 2) ? s2 : s3;
        if (g < 4 && jid < NJOB) s_raw[w][g][jid] = val;
    }
    __syncthreads();

    if (t < APP * HH) {
        const int p = t >> 2, h = t & 3;
        const float inv = 0.17677669529663687f;   // 1/sqrt(32)
        float accA = 0.0f;
        #pragma unroll
        for (int i = 0; i < SS; i++) {
            const float* raw = &s_raw[p][h][i * 18];
            float corr = raw[17] - raw[16];        // q.bk - q.Kf'[n]
            float l[KNB];
            float mx = -1e30f;
            #pragma unroll
            for (int k = 0; k < KNB; k++) {
                l[k] = inv * (raw[k] + corr);
                mx = fmaxf(mx, l[k]);
            }
            float se = 0.0f, sl = 0.0f;
            #pragma unroll
            for (int k = 0; k < KNB; k++) {
                float e = __expf(l[k] - mx);
                se += e;
                sl = fmaf(e, l[k], sl);
            }
            accA += sl / se;
        }
        s_attn[p][h] = accA;
    }
    __syncthreads();

    {
        int p = t >> 5, c4 = t & 31;
        size_t nn = (size_t)gbase + n0 + p;
        float4 vv = *(const float4*)&g_V[nn * CC + 4 * c4];
        float a = s_attn[p][c4 >> 3];
        float4 rr = make_float4(a * vv.x, a * vv.y, a * vv.z, a * vv.w);
        *(float4*)&out[nn * CC + 4 * c4] = rr;
    }
}

// ---------------------------------------------------------------------------
extern "C" void kernel_launch(void* const* d_in, const int* in_sizes, int n_in,
                              void* d_out, int out_size) {
    (void)in_sizes; (void)n_in; (void)out_size;
    const float* pcd   = (const float*)d_in[0];
    const float* coord = (const float*)d_in[1];
    const float* Wq    = (const float*)d_in[3];
    const float* bq    = (const float*)d_in[4];
    const float* Wk    = (const float*)d_in[5];
    const float* bk    = (const float*)d_in[6];
    const float* Wv    = (const float*)d_in[7];
    const float* bv    = (const float*)d_in[8];
    float* out = (float*)d_out;

    static_assert(sizeof(KnnS) <= 60 * 1024, "smem");
    cudaFuncSetAttribute(knn_kernel, cudaFuncAttributeMaxDynamicSharedMemorySize,
                         (int)sizeof(KnnS));

    knn_kernel<<<BN / 8, 256, sizeof(KnnS)>>>(coord);
    gemm_kernel<<<dim3(BN / MT, 2 + SS), 256>>>(pcd, Wq, bq, Wk, bk, Wv, bv);
    attn_kernel<<<BN / APP, 256>>>(out);
}